// round 14
// baseline (speedup 1.0000x reference)
#include <cuda_runtime.h>

#define BSZ 512
#define IN_DIM 128
#define H2 512
#define OUT_DIM 25

// Scratch (static device globals — no allocation)
__device__ float g_h[BSZ * H2];
__device__ float g_Q[BSZ * H2];
__device__ float g_K[BSZ * H2];
__device__ float g_V[BSZ * H2];

__device__ __forceinline__ float ex2f(float x) {
    float y;
    asm("ex2.approx.ftz.f32 %0, %1;" : "=f"(y) : "f"(x));
    return y;
}

// Pure fixed-pipe exp2 (no MUFU, no CVT): magic-number round-to-int +
// degree-5 Taylor on xf in [-0.5, 0.5] + exponent-field integer add.
// Valid for x <= ~0 (clamped at -120). Rel err ~2e-6.
__device__ __forceinline__ float ex2_poly(float x) {
    x = fmaxf(x, -120.0f);
    const float t = x + 12582912.0f;            // 1.5 * 2^23: mantissa = round(x)
    const int   ii = __float_as_int(t) - 0x4B400000;  // round(x) as int
    const float xi = t - 12582912.0f;           // round(x) as float
    const float xf = x - xi;                    // in [-0.5, 0.5]
    float p = 1.3333558e-3f;                    // ln2^5/120
    p = fmaf(p, xf, 9.6181292e-3f);             // ln2^4/24
    p = fmaf(p, xf, 5.5504109e-2f);             // ln2^3/6
    p = fmaf(p, xf, 2.4022651e-1f);             // ln2^2/2
    p = fmaf(p, xf, 6.9314718e-1f);             // ln2
    p = fmaf(p, xf, 1.0f);
    return __int_as_float(__float_as_int(p) + (ii << 23));
}

__device__ __forceinline__ float siluf(float x) {
    float e = ex2f(-1.44269504f * x);
    return __fdividef(x, 1.0f + e);
}

__device__ __forceinline__ unsigned long long dup2(float x) {
    unsigned long long r;
    asm("mov.b64 %0, {%1, %1};" : "=l"(r) : "f"(x));
    return r;
}
__device__ __forceinline__ void ffma2(unsigned long long& d,
                                      unsigned long long a,
                                      unsigned long long b) {
    asm("fma.rn.f32x2 %0, %1, %2, %0;" : "+l"(d) : "l"(a), "l"(b));
}
__device__ __forceinline__ void unpack2(unsigned long long v, float& lo, float& hi) {
    asm("mov.b64 {%0, %1}, %2;" : "=f"(lo), "=f"(hi) : "l"(v));
}

// ---------------------------------------------------------------------------
// gemm1: C = silu(A[512,128] @ W[512,128]^T + bias). 16x32 tile, 128 threads.
// (R11 version, verbatim)
// ---------------------------------------------------------------------------
__global__ void __launch_bounds__(128) gemm1_silu_kernel(
    const float* __restrict__ A,
    const float* __restrict__ W,
    const float* __restrict__ bias,
    float* __restrict__ C,
    int N, int Kd)
{
    __shared__ float As[2][16][20];
    __shared__ float Ws[2][16][36];

    const int tid  = threadIdx.x;
    const int tx   = tid & 15;
    const int ty   = tid >> 4;
    const int row0 = blockIdx.y * 16;
    const int col0 = blockIdx.x * 32;

    const int alrow = tid >> 2;
    const int alk   = (tid & 3) * 4;
    const int wlrow = tid >> 2;
    const int wlk   = (tid & 3) * 4;

    unsigned long long acc[2] = {0ull, 0ull};

    const int nk = Kd >> 4;
    float4 pa, pw;

    {
        if (tid < 64)
            pa = *(const float4*)&A[(row0 + alrow) * Kd + alk];
        pw = *(const float4*)&W[(col0 + wlrow) * Kd + wlk];
        if (tid < 64) {
            As[0][alk + 0][alrow] = pa.x; As[0][alk + 1][alrow] = pa.y;
            As[0][alk + 2][alrow] = pa.z; As[0][alk + 3][alrow] = pa.w;
        }
        Ws[0][wlk + 0][wlrow] = pw.x; Ws[0][wlk + 1][wlrow] = pw.y;
        Ws[0][wlk + 2][wlrow] = pw.z; Ws[0][wlk + 3][wlrow] = pw.w;
    }
    __syncthreads();

    for (int t = 0; t < nk; t++) {
        const int cur = t & 1;
        if (t + 1 < nk) {
            const int k0 = (t + 1) * 16;
            if (tid < 64)
                pa = *(const float4*)&A[(row0 + alrow) * Kd + k0 + alk];
            pw = *(const float4*)&W[(col0 + wlrow) * Kd + k0 + wlk];
        }

#pragma unroll
        for (int kk = 0; kk < 16; kk++) {
            const unsigned long long a =
                *(const unsigned long long*)&As[cur][kk][ty * 2];
            const float2 w = *(const float2*)&Ws[cur][kk][tx * 2];
            ffma2(acc[0], a, dup2(w.x));
            ffma2(acc[1], a, dup2(w.y));
        }

        if (t + 1 < nk) {
            const int nb = (t + 1) & 1;
            if (tid < 64) {
                As[nb][alk + 0][alrow] = pa.x; As[nb][alk + 1][alrow] = pa.y;
                As[nb][alk + 2][alrow] = pa.z; As[nb][alk + 3][alrow] = pa.w;
            }
            Ws[nb][wlk + 0][wlrow] = pw.x; Ws[nb][wlk + 1][wlrow] = pw.y;
            Ws[nb][wlk + 2][wlrow] = pw.z; Ws[nb][wlk + 3][wlrow] = pw.w;
            __syncthreads();
        }
    }

    const float b0 = bias[col0 + tx * 2];
    const float b1 = bias[col0 + tx * 2 + 1];
    float r00, r10, r01, r11;
    unpack2(acc[0], r00, r10);
    unpack2(acc[1], r01, r11);
    float* Crow0 = C + (row0 + ty * 2) * N + col0 + tx * 2;
    float* Crow1 = Crow0 + N;
    float2 o;
    o.x = siluf(r00 + b0); o.y = siluf(r01 + b1);
    *(float2*)Crow0 = o;
    o.x = siluf(r10 + b0); o.y = siluf(r11 + b1);
    *(float2*)Crow1 = o;
}

// ---------------------------------------------------------------------------
// QKV GEMM: 32x64 tile, 128 threads, 4x4 per thread (R5/R11 kernel, verbatim).
// ---------------------------------------------------------------------------
__global__ void __launch_bounds__(128) gemm_silu_kernel(
    const float* __restrict__ A,
    const float* __restrict__ W0, const float* __restrict__ W1, const float* __restrict__ W2,
    const float* __restrict__ bias0, const float* __restrict__ bias1, const float* __restrict__ bias2,
    float* __restrict__ C0, float* __restrict__ C1, float* __restrict__ C2,
    int N, int Kd)
{
    const float* W    = (blockIdx.z == 0) ? W0    : (blockIdx.z == 1) ? W1    : W2;
    const float* bias = (blockIdx.z == 0) ? bias0 : (blockIdx.z == 1) ? bias1 : bias2;
    float*       C    = (blockIdx.z == 0) ? C0    : (blockIdx.z == 1) ? C1    : C2;

    __shared__ float As[2][16][36];   // [buf][k][row]
    __shared__ float Ws[2][16][68];   // [buf][k][col]

    const int tid  = threadIdx.x;        // 0..127
    const int tx   = tid & 15;           // col group (4 cols)
    const int ty   = tid >> 4;           // row group (4 rows), 0..7
    const int row0 = blockIdx.y * 32;
    const int col0 = blockIdx.x * 64;

    const int alrow = tid >> 2;          // 0..31
    const int alk   = (tid & 3) * 4;
    const int wlrow = tid >> 1;          // 0..63
    const int wlk   = (tid & 1) * 8;

    unsigned long long acc[2][4];
#pragma unroll
    for (int p = 0; p < 2; p++)
#pragma unroll
        for (int c = 0; c < 4; c++) acc[p][c] = 0ull;

    const int nk = Kd >> 4;
    float4 pa, pw0, pw1;

    {
        pa  = *(const float4*)&A[(row0 + alrow) * Kd + alk];
        pw0 = *(const float4*)&W[(col0 + wlrow) * Kd + wlk];
        pw1 = *(const float4*)&W[(col0 + wlrow) * Kd + wlk + 4];
        As[0][alk + 0][alrow] = pa.x; As[0][alk + 1][alrow] = pa.y;
        As[0][alk + 2][alrow] = pa.z; As[0][alk + 3][alrow] = pa.w;
        Ws[0][wlk + 0][wlrow] = pw0.x; Ws[0][wlk + 1][wlrow] = pw0.y;
        Ws[0][wlk + 2][wlrow] = pw0.z; Ws[0][wlk + 3][wlrow] = pw0.w;
        Ws[0][wlk + 4][wlrow] = pw1.x; Ws[0][wlk + 5][wlrow] = pw1.y;
        Ws[0][wlk + 6][wlrow] = pw1.z; Ws[0][wlk + 7][wlrow] = pw1.w;
    }
    __syncthreads();

    for (int t = 0; t < nk; t++) {
        const int cur = t & 1;
        if (t + 1 < nk) {
            const int k0 = (t + 1) * 16;
            pa  = *(const float4*)&A[(row0 + alrow) * Kd + k0 + alk];
            pw0 = *(const float4*)&W[(col0 + wlrow) * Kd + k0 + wlk];
            pw1 = *(const float4*)&W[(col0 + wlrow) * Kd + k0 + wlk + 4];
        }

#pragma unroll
        for (int kk = 0; kk < 16; kk++) {
            const ulonglong2 a =
                *(const ulonglong2*)&As[cur][kk][ty * 4];
            const float4 w = *(const float4*)&Ws[cur][kk][tx * 4];
            const unsigned long long w0 = dup2(w.x);
            const unsigned long long w1 = dup2(w.y);
            const unsigned long long w2 = dup2(w.z);
            const unsigned long long w3 = dup2(w.w);
            ffma2(acc[0][0], a.x, w0);
            ffma2(acc[1][0], a.y, w0);
            ffma2(acc[0][1], a.x, w1);
            ffma2(acc[1][1], a.y, w1);
            ffma2(acc[0][2], a.x, w2);
            ffma2(acc[1][2], a.y, w2);
            ffma2(acc[0][3], a.x, w3);
            ffma2(acc[1][3], a.y, w3);
        }

        if (t + 1 < nk) {
            const int nb = (t + 1) & 1;
            As[nb][alk + 0][alrow] = pa.x; As[nb][alk + 1][alrow] = pa.y;
            As[nb][alk + 2][alrow] = pa.z; As[nb][alk + 3][alrow] = pa.w;
            Ws[nb][wlk + 0][wlrow] = pw0.x; Ws[nb][wlk + 1][wlrow] = pw0.y;
            Ws[nb][wlk + 2][wlrow] = pw0.z; Ws[nb][wlk + 3][wlrow] = pw0.w;
            Ws[nb][wlk + 4][wlrow] = pw1.x; Ws[nb][wlk + 5][wlrow] = pw1.y;
            Ws[nb][wlk + 6][wlrow] = pw1.z; Ws[nb][wlk + 7][wlrow] = pw1.w;
            __syncthreads();
        }
    }

    float bz[4];
#pragma unroll
    for (int c = 0; c < 4; c++) bz[c] = bias[col0 + tx * 4 + c];

#pragma unroll
    for (int p = 0; p < 2; p++) {
        float r0[4], r1[4];
#pragma unroll
        for (int c = 0; c < 4; c++) unpack2(acc[p][c], r0[c], r1[c]);
        float* Crow0 = C + (row0 + ty * 4 + 2 * p) * N + col0 + tx * 4;
        float* Crow1 = Crow0 + N;
        float4 o;
        o.x = siluf(r0[0] + bz[0]); o.y = siluf(r0[1] + bz[1]);
        o.z = siluf(r0[2] + bz[2]); o.w = siluf(r0[3] + bz[3]);
        *(float4*)Crow0 = o;
        o.x = siluf(r1[0] + bz[0]); o.y = siluf(r1[1] + bz[1]);
        o.z = siluf(r1[2] + bz[2]); o.w = siluf(r1[3] + bz[3]);
        *(float4*)Crow1 = o;
    }
}

// ---------------------------------------------------------------------------
// Attention + output projection + quadratic epilogue.
// scores rank-1 => row max is q*Kmax (q>=0) or q*Kmin (q<0).
// Hybrid exp: 3 of 4 lanes use MUFU ex2, 1 of 4 uses the fixed-pipe poly
// exp2 — offloads 25% of the MUFU-bound work to the idle fma/alu pipes.
// ---------------------------------------------------------------------------
__global__ void attn_out_kernel(const float* __restrict__ W_out,
                                const float* __restrict__ b_out,
                                float* __restrict__ out)
{
    __shared__ __align__(16) float Ks[H2];
    __shared__ __align__(16) float Vs[H2];
    __shared__ float cs[H2];
    __shared__ float redmax[16];
    __shared__ float redmin[16];
    __shared__ float s_kmax, s_kmin;
    __shared__ float ys[32];

    const int b = blockIdx.x;
    const int t = threadIdx.x;

    float k = g_K[b * H2 + t] * 1.44269504f;  // K * log2(e)
    Ks[t] = k;
    Vs[t] = g_V[b * H2 + t];

    float kmx = k, kmn = k;
#pragma unroll
    for (int o = 16; o; o >>= 1) {
        kmx = fmaxf(kmx, __shfl_xor_sync(0xFFFFFFFFu, kmx, o));
        kmn = fminf(kmn, __shfl_xor_sync(0xFFFFFFFFu, kmn, o));
    }
    if ((t & 31) == 0) { redmax[t >> 5] = kmx; redmin[t >> 5] = kmn; }
    __syncthreads();
    if (t == 0) {
        float a = redmax[0], bm = redmin[0];
#pragma unroll
        for (int i = 1; i < 16; i++) {
            a  = fmaxf(a,  redmax[i]);
            bm = fminf(bm, redmin[i]);
        }
        s_kmax = a; s_kmin = bm;
    }
    __syncthreads();

    const float q = g_Q[b * H2 + t];
    const float kext = (q >= 0.0f) ? s_kmax : s_kmin;
    const float c = -q * kext;  // exponent arg <= 0 guaranteed

    const float4* K4 = reinterpret_cast<const float4*>(Ks);
    const float4* V4 = reinterpret_cast<const float4*>(Vs);
    float sE = 0.0f, sEV = 0.0f;
#pragma unroll 4
    for (int j = 0; j < H2 / 4; j++) {
        const float4 k4 = K4[j];
        const float4 v4 = V4[j];
        const float e0 = ex2f(fmaf(q, k4.x, c));
        const float e1 = ex2f(fmaf(q, k4.y, c));
        const float e2 = ex2f(fmaf(q, k4.z, c));
        const float e3 = ex2_poly(fmaf(q, k4.w, c));  // fixed-pipe lane
        sE += e0; sEV = fmaf(e0, v4.x, sEV);
        sE += e1; sEV = fmaf(e1, v4.y, sEV);
        sE += e2; sEV = fmaf(e2, v4.z, sEV);
        sE += e3; sEV = fmaf(e3, v4.w, sEV);
    }
    cs[t] = siluf(__fdividef(sEV, sE));
    __syncthreads();

    // output projection: warp w handles n = w and n = w + 16 (n < 25)
    const int w = t >> 5, lane = t & 31;
#pragma unroll
    for (int r = 0; r < 2; r++) {
        int n = w + 16 * r;
        if (n < OUT_DIM) {
            const float* Wr = W_out + n * H2;
            float s = 0.0f;
#pragma unroll
            for (int kk = 0; kk < 16; kk++)
                s = fmaf(cs[lane + 32 * kk], Wr[lane + 32 * kk], s);
#pragma unroll
            for (int o = 16; o; o >>= 1)
                s += __shfl_xor_sync(0xFFFFFFFFu, s, o);
            if (lane == 0) ys[n] = siluf(s + b_out[n]);
        }
    }
    __syncthreads();

    if (t == 0) {
        float g[5];
#pragma unroll
        for (int gi = 0; gi < 5; gi++) {
            float s = 0.0f;
#pragma unroll
            for (int i = 0; i < 5; i++) {
                float yv = ys[gi * 5 + i];
                s = fmaf(yv, yv, s);
            }
            g[gi] = s;
        }
        const float m11 = g[0], m12 = g[1], m21 = g[2], m22 = g[3], mpp = g[4];
        const float q0 = ys[0], q1 = ys[1], q2 = ys[2], q3 = ys[3];
        float quad = m11 * (q0 * q0 + q1 * q1)
                   + (m12 + m21) * (q0 * q2 + q1 * q3)
                   + m22 * (q2 * q2 + q3 * q3);
        out[b] = quad + mpp;
    }
}

// ---------------------------------------------------------------------------
extern "C" void kernel_launch(void* const* d_in, const int* in_sizes, int n_in,
                              void* d_out, int out_size)
{
    const float* x     = (const float*)d_in[0];
    // d_in[1] = na (int32, always 4) — unused (q = y[:, :4] hardcoded)
    const float* W_in  = (const float*)d_in[2];
    const float* b_in  = (const float*)d_in[3];
    const float* Aq    = (const float*)d_in[4];
    const float* Bq    = (const float*)d_in[5];
    const float* Ak    = (const float*)d_in[6];
    const float* Bk    = (const float*)d_in[7];
    const float* Av    = (const float*)d_in[8];
    const float* Bv    = (const float*)d_in[9];
    const float* W_out = (const float*)d_in[10];
    const float* b_out = (const float*)d_in[11];
    float* out = (float*)d_out;

    float *h, *Qp, *Kp, *Vp;
    cudaGetSymbolAddress((void**)&h,  g_h);
    cudaGetSymbolAddress((void**)&Qp, g_Q);
    cudaGetSymbolAddress((void**)&Kp, g_K);
    cudaGetSymbolAddress((void**)&Vp, g_V);

    // h = silu(x @ W_in^T + b_in): 16x32 tiles -> 512 blocks
    gemm1_silu_kernel<<<dim3(16, 32), 128>>>(x, W_in, b_in, h, H2, IN_DIM);

    // Q,K,V = silu(h @ A*^T + B*): 32x64 tiles, fused via grid.z -> 384 blocks
    gemm_silu_kernel<<<dim3(8, 16, 3), 128>>>(
        h, Aq, Ak, Av, Bq, Bk, Bv, Qp, Kp, Vp, H2, H2);

    // rank-1 softmax attention (hybrid MUFU+poly exp) + projection + epilogue
    attn_out_kernel<<<BSZ, H2>>>(W_out, b_out, out);
}

// round 15
// speedup vs baseline: 1.0502x; 1.0502x over previous
#include <cuda_runtime.h>

#define BSZ 512
#define IN_DIM 128
#define H2 512
#define OUT_DIM 25
#define NPOLY 33   // Taylor terms m = 0..32

// Scratch (static device globals — no allocation)
__device__ float g_h[BSZ * H2];
__device__ float g_Q[BSZ * H2];
__device__ float g_K[BSZ * H2];
__device__ float g_V[BSZ * H2];

__constant__ float c_invfact[NPOLY] = {
    1.0f, 1.0f, 5.0000000e-01f, 1.6666667e-01f, 4.1666667e-02f,
    8.3333333e-03f, 1.3888889e-03f, 1.9841270e-04f, 2.4801587e-05f,
    2.7557319e-06f, 2.7557319e-07f, 2.5052108e-08f, 2.0876757e-09f,
    1.6059044e-10f, 1.1470746e-11f, 7.6471637e-13f, 4.7794773e-14f,
    2.8114573e-15f, 1.5619207e-16f, 8.2206352e-18f, 4.1103176e-19f,
    1.9572941e-20f, 8.8967914e-22f, 3.8681702e-23f, 1.6117376e-24f,
    6.4469503e-26f, 2.4795963e-27f, 9.1836898e-29f, 3.2798892e-30f,
    1.1309962e-31f, 3.7699876e-33f, 1.2161250e-34f, 3.8003907e-36f
};

__device__ __forceinline__ float ex2f(float x) {
    float y;
    asm("ex2.approx.ftz.f32 %0, %1;" : "=f"(y) : "f"(x));
    return y;
}

__device__ __forceinline__ float siluf(float x) {
    float e = ex2f(-1.44269504f * x);
    return __fdividef(x, 1.0f + e);
}

__device__ __forceinline__ unsigned long long dup2(float x) {
    unsigned long long r;
    asm("mov.b64 %0, {%1, %1};" : "=l"(r) : "f"(x));
    return r;
}
__device__ __forceinline__ void ffma2(unsigned long long& d,
                                      unsigned long long a,
                                      unsigned long long b) {
    asm("fma.rn.f32x2 %0, %1, %2, %0;" : "+l"(d) : "l"(a), "l"(b));
}
__device__ __forceinline__ void unpack2(unsigned long long v, float& lo, float& hi) {
    asm("mov.b64 {%0, %1}, %2;" : "=f"(lo), "=f"(hi) : "l"(v));
}

// ---------------------------------------------------------------------------
// gemm1: C = silu(A[512,128] @ W[512,128]^T + bias). 16x32 tile, 128 threads.
// (R11 version, verbatim)
// ---------------------------------------------------------------------------
__global__ void __launch_bounds__(128) gemm1_silu_kernel(
    const float* __restrict__ A,
    const float* __restrict__ W,
    const float* __restrict__ bias,
    float* __restrict__ C,
    int N, int Kd)
{
    __shared__ float As[2][16][20];
    __shared__ float Ws[2][16][36];

    const int tid  = threadIdx.x;
    const int tx   = tid & 15;
    const int ty   = tid >> 4;
    const int row0 = blockIdx.y * 16;
    const int col0 = blockIdx.x * 32;

    const int alrow = tid >> 2;
    const int alk   = (tid & 3) * 4;
    const int wlrow = tid >> 2;
    const int wlk   = (tid & 3) * 4;

    unsigned long long acc[2] = {0ull, 0ull};

    const int nk = Kd >> 4;
    float4 pa, pw;

    {
        if (tid < 64)
            pa = *(const float4*)&A[(row0 + alrow) * Kd + alk];
        pw = *(const float4*)&W[(col0 + wlrow) * Kd + wlk];
        if (tid < 64) {
            As[0][alk + 0][alrow] = pa.x; As[0][alk + 1][alrow] = pa.y;
            As[0][alk + 2][alrow] = pa.z; As[0][alk + 3][alrow] = pa.w;
        }
        Ws[0][wlk + 0][wlrow] = pw.x; Ws[0][wlk + 1][wlrow] = pw.y;
        Ws[0][wlk + 2][wlrow] = pw.z; Ws[0][wlk + 3][wlrow] = pw.w;
    }
    __syncthreads();

    for (int t = 0; t < nk; t++) {
        const int cur = t & 1;
        if (t + 1 < nk) {
            const int k0 = (t + 1) * 16;
            if (tid < 64)
                pa = *(const float4*)&A[(row0 + alrow) * Kd + k0 + alk];
            pw = *(const float4*)&W[(col0 + wlrow) * Kd + k0 + wlk];
        }

#pragma unroll
        for (int kk = 0; kk < 16; kk++) {
            const unsigned long long a =
                *(const unsigned long long*)&As[cur][kk][ty * 2];
            const float2 w = *(const float2*)&Ws[cur][kk][tx * 2];
            ffma2(acc[0], a, dup2(w.x));
            ffma2(acc[1], a, dup2(w.y));
        }

        if (t + 1 < nk) {
            const int nb = (t + 1) & 1;
            if (tid < 64) {
                As[nb][alk + 0][alrow] = pa.x; As[nb][alk + 1][alrow] = pa.y;
                As[nb][alk + 2][alrow] = pa.z; As[nb][alk + 3][alrow] = pa.w;
            }
            Ws[nb][wlk + 0][wlrow] = pw.x; Ws[nb][wlk + 1][wlrow] = pw.y;
            Ws[nb][wlk + 2][wlrow] = pw.z; Ws[nb][wlk + 3][wlrow] = pw.w;
            __syncthreads();
        }
    }

    const float b0 = bias[col0 + tx * 2];
    const float b1 = bias[col0 + tx * 2 + 1];
    float r00, r10, r01, r11;
    unpack2(acc[0], r00, r10);
    unpack2(acc[1], r01, r11);
    float* Crow0 = C + (row0 + ty * 2) * N + col0 + tx * 2;
    float* Crow1 = Crow0 + N;
    float2 o;
    o.x = siluf(r00 + b0); o.y = siluf(r01 + b1);
    *(float2*)Crow0 = o;
    o.x = siluf(r10 + b0); o.y = siluf(r11 + b1);
    *(float2*)Crow1 = o;
}

// ---------------------------------------------------------------------------
// QKV GEMM: 32x64 tile, 128 threads, 4x4 per thread (R5/R11 kernel, verbatim).
// ---------------------------------------------------------------------------
__global__ void __launch_bounds__(128) gemm_silu_kernel(
    const float* __restrict__ A,
    const float* __restrict__ W0, const float* __restrict__ W1, const float* __restrict__ W2,
    const float* __restrict__ bias0, const float* __restrict__ bias1, const float* __restrict__ bias2,
    float* __restrict__ C0, float* __restrict__ C1, float* __restrict__ C2,
    int N, int Kd)
{
    const float* W    = (blockIdx.z == 0) ? W0    : (blockIdx.z == 1) ? W1    : W2;
    const float* bias = (blockIdx.z == 0) ? bias0 : (blockIdx.z == 1) ? bias1 : bias2;
    float*       C    = (blockIdx.z == 0) ? C0    : (blockIdx.z == 1) ? C1    : C2;

    __shared__ float As[2][16][36];
    __shared__ float Ws[2][16][68];

    const int tid  = threadIdx.x;
    const int tx   = tid & 15;
    const int ty   = tid >> 4;
    const int row0 = blockIdx.y * 32;
    const int col0 = blockIdx.x * 64;

    const int alrow = tid >> 2;
    const int alk   = (tid & 3) * 4;
    const int wlrow = tid >> 1;
    const int wlk   = (tid & 1) * 8;

    unsigned long long acc[2][4];
#pragma unroll
    for (int p = 0; p < 2; p++)
#pragma unroll
        for (int c = 0; c < 4; c++) acc[p][c] = 0ull;

    const int nk = Kd >> 4;
    float4 pa, pw0, pw1;

    {
        pa  = *(const float4*)&A[(row0 + alrow) * Kd + alk];
        pw0 = *(const float4*)&W[(col0 + wlrow) * Kd + wlk];
        pw1 = *(const float4*)&W[(col0 + wlrow) * Kd + wlk + 4];
        As[0][alk + 0][alrow] = pa.x; As[0][alk + 1][alrow] = pa.y;
        As[0][alk + 2][alrow] = pa.z; As[0][alk + 3][alrow] = pa.w;
        Ws[0][wlk + 0][wlrow] = pw0.x; Ws[0][wlk + 1][wlrow] = pw0.y;
        Ws[0][wlk + 2][wlrow] = pw0.z; Ws[0][wlk + 3][wlrow] = pw0.w;
        Ws[0][wlk + 4][wlrow] = pw1.x; Ws[0][wlk + 5][wlrow] = pw1.y;
        Ws[0][wlk + 6][wlrow] = pw1.z; Ws[0][wlk + 7][wlrow] = pw1.w;
    }
    __syncthreads();

    for (int t = 0; t < nk; t++) {
        const int cur = t & 1;
        if (t + 1 < nk) {
            const int k0 = (t + 1) * 16;
            pa  = *(const float4*)&A[(row0 + alrow) * Kd + k0 + alk];
            pw0 = *(const float4*)&W[(col0 + wlrow) * Kd + k0 + wlk];
            pw1 = *(const float4*)&W[(col0 + wlrow) * Kd + k0 + wlk + 4];
        }

#pragma unroll
        for (int kk = 0; kk < 16; kk++) {
            const ulonglong2 a =
                *(const ulonglong2*)&As[cur][kk][ty * 4];
            const float4 w = *(const float4*)&Ws[cur][kk][tx * 4];
            const unsigned long long w0 = dup2(w.x);
            const unsigned long long w1 = dup2(w.y);
            const unsigned long long w2 = dup2(w.z);
            const unsigned long long w3 = dup2(w.w);
            ffma2(acc[0][0], a.x, w0);
            ffma2(acc[1][0], a.y, w0);
            ffma2(acc[0][1], a.x, w1);
            ffma2(acc[1][1], a.y, w1);
            ffma2(acc[0][2], a.x, w2);
            ffma2(acc[1][2], a.y, w2);
            ffma2(acc[0][3], a.x, w3);
            ffma2(acc[1][3], a.y, w3);
        }

        if (t + 1 < nk) {
            const int nb = (t + 1) & 1;
            As[nb][alk + 0][alrow] = pa.x; As[nb][alk + 1][alrow] = pa.y;
            As[nb][alk + 2][alrow] = pa.z; As[nb][alk + 3][alrow] = pa.w;
            Ws[nb][wlk + 0][wlrow] = pw0.x; Ws[nb][wlk + 1][wlrow] = pw0.y;
            Ws[nb][wlk + 2][wlrow] = pw0.z; Ws[nb][wlk + 3][wlrow] = pw0.w;
            Ws[nb][wlk + 4][wlrow] = pw1.x; Ws[nb][wlk + 5][wlrow] = pw1.y;
            Ws[nb][wlk + 6][wlrow] = pw1.z; Ws[nb][wlk + 7][wlrow] = pw1.w;
            __syncthreads();
        }
    }

    float bz[4];
#pragma unroll
    for (int c = 0; c < 4; c++) bz[c] = bias[col0 + tx * 4 + c];

#pragma unroll
    for (int p = 0; p < 2; p++) {
        float r0[4], r1[4];
#pragma unroll
        for (int c = 0; c < 4; c++) unpack2(acc[p][c], r0[c], r1[c]);
        float* Crow0 = C + (row0 + ty * 4 + 2 * p) * N + col0 + tx * 4;
        float* Crow1 = Crow0 + N;
        float4 o;
        o.x = siluf(r0[0] + bz[0]); o.y = siluf(r0[1] + bz[1]);
        o.z = siluf(r0[2] + bz[2]); o.w = siluf(r0[3] + bz[3]);
        *(float4*)Crow0 = o;
        o.x = siluf(r1[0] + bz[0]); o.y = siluf(r1[1] + bz[1]);
        o.z = siluf(r1[2] + bz[2]); o.w = siluf(r1[3] + bz[3]);
        *(float4*)Crow1 = o;
    }
}

// ---------------------------------------------------------------------------
// Attention v5: rank-1 softmax, NO SORT.
//  - q <= qc: exact Taylor-moment evaluation (33 terms; R8-validated).
//  - q >  qc: plain full-512 MUFU exp loop (exact; kext = kmax since q > 0).
//  - 2-way atomic partition groups poly/exp threads into disjoint warps so
//    the MUFU loop only runs on the ~45% of warps that need it.
// ---------------------------------------------------------------------------
__global__ void __launch_bounds__(H2) attn_out_kernel(
    const float* __restrict__ W_out,
    const float* __restrict__ b_out,
    float* __restrict__ out)
{
    __shared__ __align__(16) float Ks[H2];   // K * log2(e)
    __shared__ __align__(16) float Vs[H2];
    __shared__ float qperm[H2];
    __shared__ int   idxperm[H2];
    __shared__ float cs[H2];
    __shared__ float red[16];
    __shared__ float s_kmax;
    __shared__ float m1p[NPOLY][16];
    __shared__ float mvp[NPOLY][16];
    __shared__ float c1[NPOLY], cV[NPOLY];
    __shared__ int   cnt[2];
    __shared__ int   s_npoly;
    __shared__ float ys[32];

    const int b = blockIdx.x;
    const int t = threadIdx.x;
    const int wid = t >> 5, lane = t & 31;

    const float kv = g_K[b * H2 + t];
    const float vv = g_V[b * H2 + t];
    const float qv = g_Q[b * H2 + t];
    Ks[t] = kv * 1.44269504f;
    Vs[t] = vv;
    if (t < 2) cnt[t] = 0;

    // ---- block max of K ----
    float kmx = kv;
#pragma unroll
    for (int o = 16; o; o >>= 1)
        kmx = fmaxf(kmx, __shfl_xor_sync(0xFFFFFFFFu, kmx, o));
    if (lane == 0) red[wid] = kmx;
    __syncthreads();
    if (t == 0) {
        float a = red[0];
#pragma unroll
        for (int i = 1; i < 16; i++) a = fmaxf(a, red[i]);
        s_kmax = a;
    }
    __syncthreads();
    const float kmax = s_kmax;
    const float S    = fmaxf(kmax, 0.3f);
    const float qc   = fmaxf(7.0f / S, 0.2786f);

    // ---- moments from registers: mu_m = sum r^m, muV_m = sum r^m * V ----
    {
        const float r = kv / S;
        float pw = 1.0f;
#pragma unroll 1
        for (int m = 0; m < NPOLY; m++) {
            float s1 = pw, sv = pw * vv;
#pragma unroll
            for (int o = 16; o; o >>= 1) {
                s1 += __shfl_xor_sync(0xFFFFFFFFu, s1, o);
                sv += __shfl_xor_sync(0xFFFFFFFFu, sv, o);
            }
            if (lane == 0) { m1p[m][wid] = s1; mvp[m][wid] = sv; }
            pw *= r;
        }
    }

    // ---- 2-way partition: bkt 0 = poly (q <= qc), bkt 1 = exp ----
    const int bkt  = (qv <= qc) ? 0 : 1;
    const int rank = atomicAdd(&cnt[bkt], 1);
    __syncthreads();

    // finalize moment coefficients + partition base
    if (t == 0) s_npoly = cnt[0];
    if (t < NPOLY) {
        float a = 0.0f;
#pragma unroll
        for (int i = 0; i < 16; i++) a += m1p[t][i];
        c1[t] = a * c_invfact[t];
    } else if (t >= 64 && t < 64 + NPOLY) {
        const int m = t - 64;
        float a = 0.0f;
#pragma unroll
        for (int i = 0; i < 16; i++) a += mvp[m][i];
        cV[m] = a * c_invfact[m];
    }
    __syncthreads();

    const int npoly = s_npoly;
    {
        const int slot = (bkt == 0) ? rank : npoly + rank;
        qperm[slot]   = qv;
        idxperm[slot] = t;
    }
    __syncthreads();

    // ---- compute ctx at my slot ----
    {
        const float q   = qperm[t];
        const int   oid = idxperm[t];
        float ctx;
        if (t < npoly) {
            // Taylor-moment path (exact to ~1e-8 at |q*S| <= 7)
            const float tv = q * S;
            float num = cV[NPOLY - 1], den = c1[NPOLY - 1];
#pragma unroll
            for (int m = NPOLY - 2; m >= 0; m--) {
                num = fmaf(num, tv, cV[m]);
                den = fmaf(den, tv, c1[m]);
            }
            ctx = __fdividef(num, den);
        } else {
            // full MUFU loop; q > qc > 0 so kext = kmax
            const float c = -q * kmax * 1.44269504f;
            const float4* K4 = reinterpret_cast<const float4*>(Ks);
            const float4* V4 = reinterpret_cast<const float4*>(Vs);
            float sE = 0.0f, sEV = 0.0f;
#pragma unroll 4
            for (int j = 0; j < H2 / 4; j++) {
                const float4 k4 = K4[j];
                const float4 v4 = V4[j];
                const float e0 = ex2f(fmaf(q, k4.x, c));
                const float e1 = ex2f(fmaf(q, k4.y, c));
                const float e2 = ex2f(fmaf(q, k4.z, c));
                const float e3 = ex2f(fmaf(q, k4.w, c));
                sE += e0; sEV = fmaf(e0, v4.x, sEV);
                sE += e1; sEV = fmaf(e1, v4.y, sEV);
                sE += e2; sEV = fmaf(e2, v4.z, sEV);
                sE += e3; sEV = fmaf(e3, v4.w, sEV);
            }
            ctx = __fdividef(sEV, sE);
        }
        cs[oid] = siluf(ctx);
    }
    __syncthreads();

    // ---- output projection: warp w handles n = w and n = w + 16 ----
#pragma unroll
    for (int r = 0; r < 2; r++) {
        const int n = wid + 16 * r;
        if (n < OUT_DIM) {
            const float* Wr = W_out + n * H2;
            float s = 0.0f;
#pragma unroll
            for (int kk = 0; kk < 16; kk++)
                s = fmaf(cs[lane + 32 * kk], Wr[lane + 32 * kk], s);
#pragma unroll
            for (int o = 16; o; o >>= 1)
                s += __shfl_xor_sync(0xFFFFFFFFu, s, o);
            if (lane == 0) ys[n] = siluf(s + b_out[n]);
        }
    }
    __syncthreads();

    if (t == 0) {
        float g[5];
#pragma unroll
        for (int gi = 0; gi < 5; gi++) {
            float s = 0.0f;
#pragma unroll
            for (int i = 0; i < 5; i++) {
                const float yv = ys[gi * 5 + i];
                s = fmaf(yv, yv, s);
            }
            g[gi] = s;
        }
        const float m11 = g[0], m12 = g[1], m21 = g[2], m22 = g[3], mpp = g[4];
        const float q0 = ys[0], q1 = ys[1], q2 = ys[2], q3 = ys[3];
        const float quad = m11 * (q0 * q0 + q1 * q1)
                         + (m12 + m21) * (q0 * q2 + q1 * q3)
                         + m22 * (q2 * q2 + q3 * q3);
        out[b] = quad + mpp;
    }
}

// ---------------------------------------------------------------------------
extern "C" void kernel_launch(void* const* d_in, const int* in_sizes, int n_in,
                              void* d_out, int out_size)
{
    const float* x     = (const float*)d_in[0];
    // d_in[1] = na (int32, always 4) — unused (q = y[:, :4] hardcoded)
    const float* W_in  = (const float*)d_in[2];
    const float* b_in  = (const float*)d_in[3];
    const float* Aq    = (const float*)d_in[4];
    const float* Bq    = (const float*)d_in[5];
    const float* Ak    = (const float*)d_in[6];
    const float* Bk    = (const float*)d_in[7];
    const float* Av    = (const float*)d_in[8];
    const float* Bv    = (const float*)d_in[9];
    const float* W_out = (const float*)d_in[10];
    const float* b_out = (const float*)d_in[11];
    float* out = (float*)d_out;

    float *h, *Qp, *Kp, *Vp;
    cudaGetSymbolAddress((void**)&h,  g_h);
    cudaGetSymbolAddress((void**)&Qp, g_Q);
    cudaGetSymbolAddress((void**)&Kp, g_K);
    cudaGetSymbolAddress((void**)&Vp, g_V);

    // h = silu(x @ W_in^T + b_in): 16x32 tiles -> 512 blocks
    gemm1_silu_kernel<<<dim3(16, 32), 128>>>(x, W_in, b_in, h, H2, IN_DIM);

    // Q,K,V = silu(h @ A*^T + B*): 32x64 tiles, fused via grid.z -> 384 blocks
    gemm_silu_kernel<<<dim3(8, 16, 3), 128>>>(
        h, Aq, Ak, Av, Bq, Bk, Bv, Qp, Kp, Vp, H2, H2);

    // rank-1 softmax attention (poly + full-exp, partitioned) + epilogue
    attn_out_kernel<<<BSZ, H2>>>(W_out, b_out, out);
}

// round 16
// speedup vs baseline: 1.1766x; 1.1204x over previous
#include <cuda_runtime.h>

#define BSZ 512
#define IN_DIM 128
#define H2 512
#define OUT_DIM 25
#define NNODE 32
#define NBIN 32

// Scratch (static device globals — no allocation)
__device__ float g_h[BSZ * H2];
__device__ float g_Q[BSZ * H2];
__device__ float g_K[BSZ * H2];
__device__ float g_V[BSZ * H2];

// Chebyshev (1st kind, N=32): cos(theta_m), w_m = (-1)^m sin(theta_m),
// theta_m = (2m+1)*pi/64. Exact constants (consistent node/weight pairs).
__constant__ float c_ncos[NNODE] = {
     0.9987955f,  0.9891765f,  0.9700313f,  0.9415441f,
     0.9039893f,  0.8577286f,  0.8032075f,  0.7409511f,
     0.6715590f,  0.5956993f,  0.5141027f,  0.4275551f,
     0.3368899f,  0.2429802f,  0.1467305f,  0.0490677f,
    -0.0490677f, -0.1467305f, -0.2429802f, -0.3368899f,
    -0.4275551f, -0.5141027f, -0.5956993f, -0.6715590f,
    -0.7409511f, -0.8032075f, -0.8577286f, -0.9039893f,
    -0.9415441f, -0.9700313f, -0.9891765f, -0.9987955f
};
__constant__ float c_nw[NNODE] = {
     0.0490677f, -0.1467305f,  0.2429802f, -0.3368899f,
     0.4275551f, -0.5141027f,  0.5956993f, -0.6715590f,
     0.7409511f, -0.8032075f,  0.8577286f, -0.9039893f,
     0.9415441f, -0.9700313f,  0.9891765f, -0.9987955f,
     0.9987955f, -0.9891765f,  0.9700313f, -0.9415441f,
     0.9039893f, -0.8577286f,  0.8032075f, -0.7409511f,
     0.6715590f, -0.5956993f,  0.5141027f, -0.4275551f,
     0.3368899f, -0.2429802f,  0.1467305f, -0.0490677f
};

__device__ __forceinline__ float ex2f(float x) {
    float y;
    asm("ex2.approx.ftz.f32 %0, %1;" : "=f"(y) : "f"(x));
    return y;
}

__device__ __forceinline__ float siluf(float x) {
    float e = ex2f(-1.44269504f * x);
    return __fdividef(x, 1.0f + e);
}

__device__ __forceinline__ unsigned long long dup2(float x) {
    unsigned long long r;
    asm("mov.b64 %0, {%1, %1};" : "=l"(r) : "f"(x));
    return r;
}
__device__ __forceinline__ void ffma2(unsigned long long& d,
                                      unsigned long long a,
                                      unsigned long long b) {
    asm("fma.rn.f32x2 %0, %1, %2, %0;" : "+l"(d) : "l"(a), "l"(b));
}
__device__ __forceinline__ void unpack2(unsigned long long v, float& lo, float& hi) {
    asm("mov.b64 {%0, %1}, %2;" : "=f"(lo), "=f"(hi) : "l"(v));
}

// ---------------------------------------------------------------------------
// gemm1: C = silu(A[512,128] @ W[512,128]^T + bias). 16x32 tile, 128 threads.
// (R11 version, verbatim)
// ---------------------------------------------------------------------------
__global__ void __launch_bounds__(128) gemm1_silu_kernel(
    const float* __restrict__ A,
    const float* __restrict__ W,
    const float* __restrict__ bias,
    float* __restrict__ C,
    int N, int Kd)
{
    __shared__ float As[2][16][20];
    __shared__ float Ws[2][16][36];

    const int tid  = threadIdx.x;
    const int tx   = tid & 15;
    const int ty   = tid >> 4;
    const int row0 = blockIdx.y * 16;
    const int col0 = blockIdx.x * 32;

    const int alrow = tid >> 2;
    const int alk   = (tid & 3) * 4;
    const int wlrow = tid >> 2;
    const int wlk   = (tid & 3) * 4;

    unsigned long long acc[2] = {0ull, 0ull};

    const int nk = Kd >> 4;
    float4 pa, pw;

    {
        if (tid < 64)
            pa = *(const float4*)&A[(row0 + alrow) * Kd + alk];
        pw = *(const float4*)&W[(col0 + wlrow) * Kd + wlk];
        if (tid < 64) {
            As[0][alk + 0][alrow] = pa.x; As[0][alk + 1][alrow] = pa.y;
            As[0][alk + 2][alrow] = pa.z; As[0][alk + 3][alrow] = pa.w;
        }
        Ws[0][wlk + 0][wlrow] = pw.x; Ws[0][wlk + 1][wlrow] = pw.y;
        Ws[0][wlk + 2][wlrow] = pw.z; Ws[0][wlk + 3][wlrow] = pw.w;
    }
    __syncthreads();

    for (int t = 0; t < nk; t++) {
        const int cur = t & 1;
        if (t + 1 < nk) {
            const int k0 = (t + 1) * 16;
            if (tid < 64)
                pa = *(const float4*)&A[(row0 + alrow) * Kd + k0 + alk];
            pw = *(const float4*)&W[(col0 + wlrow) * Kd + k0 + wlk];
        }

#pragma unroll
        for (int kk = 0; kk < 16; kk++) {
            const unsigned long long a =
                *(const unsigned long long*)&As[cur][kk][ty * 2];
            const float2 w = *(const float2*)&Ws[cur][kk][tx * 2];
            ffma2(acc[0], a, dup2(w.x));
            ffma2(acc[1], a, dup2(w.y));
        }

        if (t + 1 < nk) {
            const int nb = (t + 1) & 1;
            if (tid < 64) {
                As[nb][alk + 0][alrow] = pa.x; As[nb][alk + 1][alrow] = pa.y;
                As[nb][alk + 2][alrow] = pa.z; As[nb][alk + 3][alrow] = pa.w;
            }
            Ws[nb][wlk + 0][wlrow] = pw.x; Ws[nb][wlk + 1][wlrow] = pw.y;
            Ws[nb][wlk + 2][wlrow] = pw.z; Ws[nb][wlk + 3][wlrow] = pw.w;
            __syncthreads();
        }
    }

    const float b0 = bias[col0 + tx * 2];
    const float b1 = bias[col0 + tx * 2 + 1];
    float r00, r10, r01, r11;
    unpack2(acc[0], r00, r10);
    unpack2(acc[1], r01, r11);
    float* Crow0 = C + (row0 + ty * 2) * N + col0 + tx * 2;
    float* Crow1 = Crow0 + N;
    float2 o;
    o.x = siluf(r00 + b0); o.y = siluf(r01 + b1);
    *(float2*)Crow0 = o;
    o.x = siluf(r10 + b0); o.y = siluf(r11 + b1);
    *(float2*)Crow1 = o;
}

// ---------------------------------------------------------------------------
// QKV GEMM: 32x64 tile, 128 threads, 4x4 per thread (R5/R11 kernel, verbatim).
// ---------------------------------------------------------------------------
__global__ void __launch_bounds__(128) gemm_silu_kernel(
    const float* __restrict__ A,
    const float* __restrict__ W0, const float* __restrict__ W1, const float* __restrict__ W2,
    const float* __restrict__ bias0, const float* __restrict__ bias1, const float* __restrict__ bias2,
    float* __restrict__ C0, float* __restrict__ C1, float* __restrict__ C2,
    int N, int Kd)
{
    const float* W    = (blockIdx.z == 0) ? W0    : (blockIdx.z == 1) ? W1    : W2;
    const float* bias = (blockIdx.z == 0) ? bias0 : (blockIdx.z == 1) ? bias1 : bias2;
    float*       C    = (blockIdx.z == 0) ? C0    : (blockIdx.z == 1) ? C1    : C2;

    __shared__ float As[2][16][36];
    __shared__ float Ws[2][16][68];

    const int tid  = threadIdx.x;
    const int tx   = tid & 15;
    const int ty   = tid >> 4;
    const int row0 = blockIdx.y * 32;
    const int col0 = blockIdx.x * 64;

    const int alrow = tid >> 2;
    const int alk   = (tid & 3) * 4;
    const int wlrow = tid >> 1;
    const int wlk   = (tid & 1) * 8;

    unsigned long long acc[2][4];
#pragma unroll
    for (int p = 0; p < 2; p++)
#pragma unroll
        for (int c = 0; c < 4; c++) acc[p][c] = 0ull;

    const int nk = Kd >> 4;
    float4 pa, pw0, pw1;

    {
        pa  = *(const float4*)&A[(row0 + alrow) * Kd + alk];
        pw0 = *(const float4*)&W[(col0 + wlrow) * Kd + wlk];
        pw1 = *(const float4*)&W[(col0 + wlrow) * Kd + wlk + 4];
        As[0][alk + 0][alrow] = pa.x; As[0][alk + 1][alrow] = pa.y;
        As[0][alk + 2][alrow] = pa.z; As[0][alk + 3][alrow] = pa.w;
        Ws[0][wlk + 0][wlrow] = pw0.x; Ws[0][wlk + 1][wlrow] = pw0.y;
        Ws[0][wlk + 2][wlrow] = pw0.z; Ws[0][wlk + 3][wlrow] = pw0.w;
        Ws[0][wlk + 4][wlrow] = pw1.x; Ws[0][wlk + 5][wlrow] = pw1.y;
        Ws[0][wlk + 6][wlrow] = pw1.z; Ws[0][wlk + 7][wlrow] = pw1.w;
    }
    __syncthreads();

    for (int t = 0; t < nk; t++) {
        const int cur = t & 1;
        if (t + 1 < nk) {
            const int k0 = (t + 1) * 16;
            pa  = *(const float4*)&A[(row0 + alrow) * Kd + k0 + alk];
            pw0 = *(const float4*)&W[(col0 + wlrow) * Kd + k0 + wlk];
            pw1 = *(const float4*)&W[(col0 + wlrow) * Kd + k0 + wlk + 4];
        }

#pragma unroll
        for (int kk = 0; kk < 16; kk++) {
            const ulonglong2 a =
                *(const ulonglong2*)&As[cur][kk][ty * 4];
            const float4 w = *(const float4*)&Ws[cur][kk][tx * 4];
            const unsigned long long w0 = dup2(w.x);
            const unsigned long long w1 = dup2(w.y);
            const unsigned long long w2 = dup2(w.z);
            const unsigned long long w3 = dup2(w.w);
            ffma2(acc[0][0], a.x, w0);
            ffma2(acc[1][0], a.y, w0);
            ffma2(acc[0][1], a.x, w1);
            ffma2(acc[1][1], a.y, w1);
            ffma2(acc[0][2], a.x, w2);
            ffma2(acc[1][2], a.y, w2);
            ffma2(acc[0][3], a.x, w3);
            ffma2(acc[1][3], a.y, w3);
        }

        if (t + 1 < nk) {
            const int nb = (t + 1) & 1;
            As[nb][alk + 0][alrow] = pa.x; As[nb][alk + 1][alrow] = pa.y;
            As[nb][alk + 2][alrow] = pa.z; As[nb][alk + 3][alrow] = pa.w;
            Ws[nb][wlk + 0][wlrow] = pw0.x; Ws[nb][wlk + 1][wlrow] = pw0.y;
            Ws[nb][wlk + 2][wlrow] = pw0.z; Ws[nb][wlk + 3][wlrow] = pw0.w;
            Ws[nb][wlk + 4][wlrow] = pw1.x; Ws[nb][wlk + 5][wlrow] = pw1.y;
            Ws[nb][wlk + 6][wlrow] = pw1.z; Ws[nb][wlk + 7][wlrow] = pw1.w;
            __syncthreads();
        }
    }

    float bz[4];
#pragma unroll
    for (int c = 0; c < 4; c++) bz[c] = bias[col0 + tx * 4 + c];

#pragma unroll
    for (int p = 0; p < 2; p++) {
        float r0[4], r1[4];
#pragma unroll
        for (int c = 0; c < 4; c++) unpack2(acc[p][c], r0[c], r1[c]);
        float* Crow0 = C + (row0 + ty * 4 + 2 * p) * N + col0 + tx * 4;
        float* Crow1 = Crow0 + N;
        float4 o;
        o.x = siluf(r0[0] + bz[0]); o.y = siluf(r0[1] + bz[1]);
        o.z = siluf(r0[2] + bz[2]); o.w = siluf(r0[3] + bz[3]);
        *(float4*)Crow0 = o;
        o.x = siluf(r1[0] + bz[0]); o.y = siluf(r1[1] + bz[1]);
        o.z = siluf(r1[2] + bz[2]); o.w = siluf(r1[3] + bz[3]);
        *(float4*)Crow1 = o;
    }
}

// ---------------------------------------------------------------------------
// Attention v6: rank-1 softmax via
//  (a) Chebyshev barycentric interpolation of num(q), den(q) for q <= b
//      (32 nodes, half-width 10 e-units: error ~e^-21, NaN-guarded), and
//  (b) bin-truncated exp for q > b: 32-bin counting sort of kappa (cheap,
//      no bitonic), per-thread trip count from histogram prefix (conservative,
//      top bin always included so sE >= 1), warps grouped by trip bucket.
// ---------------------------------------------------------------------------
__global__ void __launch_bounds__(H2) attn_out_kernel(
    const float* __restrict__ W_out,
    const float* __restrict__ b_out,
    float* __restrict__ out)
{
    __shared__ float Kk[H2];       // kappa = K * log2(e), original order
    __shared__ float Vv[H2];
    __shared__ float Ksrt[H2];     // bin-ordered (descending bins)
    __shared__ float Vsrt[H2];
    __shared__ float qperm[H2];
    __shared__ int   nperm[H2];    // trip count; -1 = interp path
    __shared__ int   idxperm[H2];
    __shared__ float cs[H2];
    __shared__ float redmx[16];
    __shared__ float redmn[16];
    __shared__ float s_kmax, s_kmin;
    __shared__ float nodeq[NNODE], nden[NNODE], nnum[NNODE];
    __shared__ int   hist[NBIN], hoff[NBIN], hpre[NBIN + 1];
    __shared__ int   cnt[8], cbase[8];
    __shared__ float ys[32];

    const int b = blockIdx.x;
    const int t = threadIdx.x;
    const int wid = t >> 5, lane = t & 31;

    const float kap = g_K[b * H2 + t] * 1.44269504f;
    const float vv  = g_V[b * H2 + t];
    const float qv  = g_Q[b * H2 + t];
    Kk[t] = kap;
    Vv[t] = vv;
    if (t < NBIN) hist[t] = 0;
    if (t < 8)    cnt[t] = 0;

    // ---- block max/min of kappa ----
    float mx = kap, mn = kap;
#pragma unroll
    for (int o = 16; o; o >>= 1) {
        mx = fmaxf(mx, __shfl_xor_sync(0xFFFFFFFFu, mx, o));
        mn = fminf(mn, __shfl_xor_sync(0xFFFFFFFFu, mn, o));
    }
    if (lane == 0) { redmx[wid] = mx; redmn[wid] = mn; }
    __syncthreads();
    if (t == 0) {
        float a = redmx[0], bm = redmn[0];
#pragma unroll
        for (int i = 1; i < 16; i++) {
            a  = fmaxf(a,  redmx[i]);
            bm = fminf(bm, redmn[i]);
        }
        s_kmax = a; s_kmin = bm;
    }
    __syncthreads();
    const float kapmax = s_kmax;
    const float kapmin = s_kmin;
    // interval in q: [qa, qb], half-width 10 e-units of the stiffest term
    const float kbound = fmaxf(kapmax * 0.69314718f, 0.3f);  // natural-units
    const float qa = -0.2790f;
    const float qb = qa + 20.0f / kbound;
    const float qcen = 0.5f * (qa + qb);
    const float qhal = 0.5f * (qb - qa);

    // ---- histogram of kappa (bin 0 = highest) ----
    const float bw = (kapmax - kapmin) * (1.0f / NBIN) + 1e-20f;
    int mybin = (int)((kapmax - kap) / bw);
    mybin = (mybin > NBIN - 1) ? NBIN - 1 : ((mybin < 0) ? 0 : mybin);
    atomicAdd(&hist[mybin], 1);

    // ---- Chebyshev node evaluation: warp w -> nodes 2w, 2w+1 ----
#pragma unroll
    for (int e = 0; e < 2; e++) {
        const int m = wid * 2 + e;
        const float x = fmaf(qhal, c_ncos[m], qcen);
        float s1 = 0.0f, sv = 0.0f;
        for (int j = lane; j < H2; j += 32) {
            const float ev = ex2f(x * Kk[j]);
            s1 += ev;
            sv = fmaf(ev, Vv[j], sv);
        }
#pragma unroll
        for (int o = 16; o; o >>= 1) {
            s1 += __shfl_xor_sync(0xFFFFFFFFu, s1, o);
            sv += __shfl_xor_sync(0xFFFFFFFFu, sv, o);
        }
        if (lane == 0) { nodeq[m] = x; nden[m] = s1; nnum[m] = sv; }
    }
    __syncthreads();

    // ---- histogram prefix (serial, 32 bins) ----
    if (t == 0) {
        int s = 0;
#pragma unroll
        for (int i = 0; i < NBIN; i++) {
            hpre[i] = s; hoff[i] = s; s += hist[i];
        }
        hpre[NBIN] = s;
    }
    __syncthreads();

    // ---- scatter K,V into bin order; compute trip count + bucket ----
    {
        const int slot = atomicAdd(&hoff[mybin], 1);
        Ksrt[slot] = kap;
        Vsrt[slot] = vv;
    }
    int bkt, n = 0;
    if (qv <= qb) {
        bkt = 6;   // interp path
    } else {
        const float fb = (30.0f / qv) / bw;      // bins to keep (float, safe)
        const int Bcut = (fb >= (float)(NBIN - 1)) ? (NBIN - 1) : (int)fb;
        n = hpre[Bcut + 1];                      // >= hist[0] >= 1
        bkt = (n <= 16) ? 0 : (n <= 32) ? 1 : (n <= 64) ? 2
            : (n <= 128) ? 3 : (n <= 256) ? 4 : 5;
    }
    const int rank = atomicAdd(&cnt[bkt], 1);
    __syncthreads();
    if (t == 0) {
        int s = 0;
#pragma unroll
        for (int i = 0; i < 8; i++) { cbase[i] = s; s += cnt[i]; }
    }
    __syncthreads();
    {
        const int slot = cbase[bkt] + rank;
        qperm[slot]   = qv;
        nperm[slot]   = (bkt == 6) ? -1 : n;
        idxperm[slot] = t;
    }
    __syncthreads();

    // ---- compute ctx at my slot ----
    {
        const float q   = qperm[t];
        const int   nn  = nperm[t];
        const int   oid = idxperm[t];
        float ctx;
        if (nn < 0) {
            // barycentric ratio: ctx = sum(lam*num) / sum(lam*den)
            float sn = 0.0f, sd = 0.0f;
#pragma unroll
            for (int m = 0; m < NNODE; m++) {
                float d = q - nodeq[m];
                if (fabsf(d) < 1e-12f) d = (d >= 0.0f) ? 1e-12f : -1e-12f;
                const float lam = __fdividef(c_nw[m], d);
                sn = fmaf(lam, nnum[m], sn);
                sd = fmaf(lam, nden[m], sd);
            }
            ctx = __fdividef(sn, sd);
        } else {
            // truncated exp over bin-ordered terms; top bin included -> sE >= 1
            const float c2 = -q * kapmax;
            float sE = 0.0f, sEV = 0.0f;
            for (int j = 0; j < nn; j++) {
                const float e = ex2f(fmaf(q, Ksrt[j], c2));
                sE += e;
                sEV = fmaf(e, Vsrt[j], sEV);
            }
            ctx = __fdividef(sEV, sE);
        }
        cs[oid] = siluf(ctx);
    }
    __syncthreads();

    // ---- output projection: warp w handles n = w and n = w + 16 ----
#pragma unroll
    for (int r = 0; r < 2; r++) {
        const int no = wid + 16 * r;
        if (no < OUT_DIM) {
            const float* Wr = W_out + no * H2;
            float s = 0.0f;
#pragma unroll
            for (int kk = 0; kk < 16; kk++)
                s = fmaf(cs[lane + 32 * kk], Wr[lane + 32 * kk], s);
#pragma unroll
            for (int o = 16; o; o >>= 1)
                s += __shfl_xor_sync(0xFFFFFFFFu, s, o);
            if (lane == 0) ys[no] = siluf(s + b_out[no]);
        }
    }
    __syncthreads();

    if (t == 0) {
        float g[5];
#pragma unroll
        for (int gi = 0; gi < 5; gi++) {
            float s = 0.0f;
#pragma unroll
            for (int i = 0; i < 5; i++) {
                const float yv = ys[gi * 5 + i];
                s = fmaf(yv, yv, s);
            }
            g[gi] = s;
        }
        const float m11 = g[0], m12 = g[1], m21 = g[2], m22 = g[3], mpp = g[4];
        const float q0 = ys[0], q1 = ys[1], q2 = ys[2], q3 = ys[3];
        const float quad = m11 * (q0 * q0 + q1 * q1)
                         + (m12 + m21) * (q0 * q2 + q1 * q3)
                         + m22 * (q2 * q2 + q3 * q3);
        out[b] = quad + mpp;
    }
}

// ---------------------------------------------------------------------------
extern "C" void kernel_launch(void* const* d_in, const int* in_sizes, int n_in,
                              void* d_out, int out_size)
{
    const float* x     = (const float*)d_in[0];
    // d_in[1] = na (int32, always 4) — unused (q = y[:, :4] hardcoded)
    const float* W_in  = (const float*)d_in[2];
    const float* b_in  = (const float*)d_in[3];
    const float* Aq    = (const float*)d_in[4];
    const float* Bq    = (const float*)d_in[5];
    const float* Ak    = (const float*)d_in[6];
    const float* Bk    = (const float*)d_in[7];
    const float* Av    = (const float*)d_in[8];
    const float* Bv    = (const float*)d_in[9];
    const float* W_out = (const float*)d_in[10];
    const float* b_out = (const float*)d_in[11];
    float* out = (float*)d_out;

    float *h, *Qp, *Kp, *Vp;
    cudaGetSymbolAddress((void**)&h,  g_h);
    cudaGetSymbolAddress((void**)&Qp, g_Q);
    cudaGetSymbolAddress((void**)&Kp, g_K);
    cudaGetSymbolAddress((void**)&Vp, g_V);

    // h = silu(x @ W_in^T + b_in): 16x32 tiles -> 512 blocks
    gemm1_silu_kernel<<<dim3(16, 32), 128>>>(x, W_in, b_in, h, H2, IN_DIM);

    // Q,K,V = silu(h @ A*^T + B*): 32x64 tiles, fused via grid.z -> 384 blocks
    gemm_silu_kernel<<<dim3(8, 16, 3), 128>>>(
        h, Aq, Ak, Av, Bq, Bk, Bv, Qp, Kp, Vp, H2, H2);

    // rank-1 softmax attention (Chebyshev interp + bin-truncated exp)
    attn_out_kernel<<<BSZ, H2>>>(W_out, b_out, out);
}